// round 9
// baseline (speedup 1.0000x reference)
#include <cuda_runtime.h>
#include <cuda_bf16.h>
#include <math.h>
#include <stdint.h>

#define NB 8
#define NV 8192
#define NH 128
#define NK 128
#define NNZV 57344
#define BV (NB*NV)            // 65536
#define EROWS (1+2*NV)        // 16385
#define VCH 32
#define VCHROWS 256
#define NVK 8388608           // NB*NV*NK

// ---------------- fp32 scratch ----------------
__device__ float g_part[(size_t)NB*VCH*NK*NH];   // 16.8MB
__device__ float g_x1[(size_t)BV*256];           // 67MB
__device__ float g_x2[(size_t)BV*128];           // 33.5MB

// ---------------- bf16 hi/lo operand arrays ----------------
__device__ __align__(256) __nv_bfloat16 g_mTh[NB*NH*NK], g_mTl[NB*NH*NK];
__device__ __align__(256) __nv_bfloat16 g_Uh[NVK],  g_Ul[NVK];
__device__ __align__(256) __nv_bfloat16 g_hh[NVK],  g_hl[NVK];
__device__ __align__(256) __nv_bfloat16 g_hph[NVK], g_hpl[NVK];
__device__ __align__(256) __nv_bfloat16 g_hgh[NVK], g_hgl[NVK];
__device__ __align__(256) __nv_bfloat16 g_gxh[NVK], g_gxl[NVK];
__device__ __align__(256) __nv_bfloat16 g_gyh[NVK], g_gyl[NVK];
__device__ __align__(256) __nv_bfloat16 g_a1h[(size_t)BV*256], g_a1l[(size_t)BV*256];
__device__ __align__(256) __nv_bfloat16 g_W1h[256*384], g_W1l[256*384];
__device__ __align__(256) __nv_bfloat16 g_W2h[128*256], g_W2l[128*256];
__device__ __align__(256) __nv_bfloat16 g_Wgh[128*128], g_Wgl[128*128];
__device__ __align__(256) __nv_bfloat16 g_Wg2h[128*128], g_Wg2l[128*128];

__device__ float g_sum1[256], g_sq1[256], g_scale1[256], g_shift1[256];
__device__ float g_sum2[128], g_sq2[128], g_scale2[128], g_shift2[128];
__device__ int   g_cnt[BV], g_cur[BV], g_off[BV];
__device__ int   g_perm[NB*NNZV];

// ---------------- PTX helpers ----------------
__device__ __forceinline__ uint32_t s2u(const void* p){
    uint32_t a;
    asm("{ .reg .u64 t; cvta.to.shared.u64 t, %1; cvt.u32.u64 %0, t; }" : "=r"(a) : "l"(p));
    return a;
}
#define CP_ASYNC16(dst, src) asm volatile("cp.async.cg.shared.global [%0], [%1], 16;" :: "r"(dst), "l"(src))
#define CP_COMMIT()          asm volatile("cp.async.commit_group;" ::: "memory")
#define CP_WAIT0()           asm volatile("cp.async.wait_group 0;" ::: "memory")
#define CP_WAIT1()           asm volatile("cp.async.wait_group 1;" ::: "memory")

__device__ __forceinline__ void ldmx4(uint32_t* r, uint32_t a){
    asm volatile("ldmatrix.sync.aligned.m8n8.x4.shared.b16 {%0,%1,%2,%3}, [%4];"
        : "=r"(r[0]),"=r"(r[1]),"=r"(r[2]),"=r"(r[3]) : "r"(a));
}
__device__ __forceinline__ void ldmx2(uint32_t* r, uint32_t a){
    asm volatile("ldmatrix.sync.aligned.m8n8.x2.shared.b16 {%0,%1}, [%2];"
        : "=r"(r[0]),"=r"(r[1]) : "r"(a));
}
__device__ __forceinline__ void mmab(float* c, const uint32_t* a, const uint32_t* b){
    asm volatile("mma.sync.aligned.m16n8k16.row.col.f32.bf16.bf16.f32 "
        "{%0,%1,%2,%3}, {%4,%5,%6,%7}, {%8,%9}, {%0,%1,%2,%3};"
        : "+f"(c[0]),"+f"(c[1]),"+f"(c[2]),"+f"(c[3])
        : "r"(a[0]),"r"(a[1]),"r"(a[2]),"r"(a[3]), "r"(b[0]),"r"(b[1]));
}

// ---------------- cp.async tile loaders (chunk-XOR swizzle: cb ^= row&7) ----------------
__device__ __forceinline__ void cpa_tile256(uint32_t sdst, const __nv_bfloat16* g,
                                            int rows, int rowstride, int t, int nthr){
    for (int i = t; i < rows*16; i += nthr){
        int r = i>>4, cb = i&15;
        CP_ASYNC16(sdst + r*256 + ((cb ^ (r&7))*16), g + (size_t)r*rowstride + cb*8);
    }
}
__device__ __forceinline__ void cpa_tile128(uint32_t sdst, const __nv_bfloat16* g,
                                            int rows, int rowstride, int t, int nthr){
    for (int i = t; i < rows*8; i += nthr){
        int r = i>>3, cb = i&7;
        CP_ASYNC16(sdst + r*128 + ((cb ^ (r&7))*16), g + (size_t)r*rowstride + cb*8);
    }
}
__device__ __forceinline__ void ldA256(uint32_t* fr, uint32_t base, int m0, int ks, int lane){
    int r = m0 + (lane&15), cb = ks*2 + (lane>>4);
    ldmx4(fr, base + r*256 + ((cb ^ (r&7))*16));
}
__device__ __forceinline__ void ldB256(uint32_t* fr, uint32_t base, int n0, int ks, int lane){
    int r = n0 + (lane&7), cb = ks*2 + ((lane>>3)&1);
    ldmx2(fr, base + r*256 + ((cb ^ (r&7))*16));
}
__device__ __forceinline__ void ldA128(uint32_t* fr, uint32_t base, int m0, int ks, int lane){
    int r = m0 + (lane&15), cb = ks*2 + (lane>>4);
    ldmx4(fr, base + r*128 + ((cb ^ (r&7))*16));
}
__device__ __forceinline__ void ldB128(uint32_t* fr, uint32_t base, int n0, int ks, int lane){
    int r = n0 + (lane&7), cb = ks*2 + ((lane>>3)&1);
    ldmx2(fr, base + r*128 + ((cb ^ (r&7))*16));
}

// ---------------- bf16 split ----------------
__device__ __forceinline__ void splitf(float v, __nv_bfloat16 &hi, __nv_bfloat16 &lo){
    hi = __float2bfloat16(v);
    lo = __float2bfloat16(v - __bfloat162float(hi));
}
__device__ __forceinline__ void st_pair(__nv_bfloat16* ph, __nv_bfloat16* pl, float a, float b){
    __nv_bfloat16 ha,la,hb,lb; splitf(a,ha,la); splitf(b,hb,lb);
    __nv_bfloat162 H; H.x=ha; H.y=hb;
    __nv_bfloat162 L; L.x=la; L.y=lb;
    *(__nv_bfloat162*)ph = H;
    *(__nv_bfloat162*)pl = L;
}

// ---------------- zero small state ----------------
__global__ void k_zero() {
    int i = blockIdx.x*blockDim.x + threadIdx.x;
    if (i < BV) { g_cnt[i] = 0; g_cur[i] = 0; }
    if (i < 256) { g_sum1[i] = 0.f; g_sq1[i] = 0.f; }
    if (i < 128) { g_sum2[i] = 0.f; g_sq2[i] = 0.f; }
}

// ---------------- prep: split W1,W2,Wg,Wg2,U,h to bf16 hi/lo ----------------
__global__ void k_prep1(const float* __restrict__ W1, const float* __restrict__ W2,
                        const float* __restrict__ Wg, const float* __restrict__ Wg2,
                        const float* __restrict__ eigs, const float* __restrict__ h) {
    int i = blockIdx.x*blockDim.x + threadIdx.x;
    if (i < 98304)        { splitf(W1[i],  g_W1h[i],  g_W1l[i]); }
    else if (i < 131072)  { int j = i - 98304;  splitf(W2[j],  g_W2h[j],  g_W2l[j]); }
    else if (i < 147456)  { int j = i - 131072; splitf(Wg[j],  g_Wgh[j],  g_Wgl[j]); }
    else if (i < 163840)  { int j = i - 147456; splitf(Wg2[j], g_Wg2h[j], g_Wg2l[j]); }
    else if (i < 163840 + NVK) {
        int j = i - 163840;
        int b = j >> 20, r = j & 1048575;       // NV*NK = 2^20
        float v = eigs[(size_t)b*EROWS*NK + NK + r];   // U rows start at 1
        splitf(v, g_Uh[j], g_Ul[j]);
    } else if (i < 163840 + 2*NVK) {
        int j = i - 163840 - NVK;
        splitf(h[j], g_hh[j], g_hl[j]);
    }
}

// ---------------- spectral down (FFMA): part[k,h] = sum_v Ut[v,k]*h[v,h] ----------------
__global__ __launch_bounds__(256) void k_specdown(const float* __restrict__ eigs,
                                                  const float* __restrict__ h) {
    int c = blockIdx.x, b = blockIdx.y;
    int t = threadIdx.x, tx = t & 15, ty = t >> 4;
    __shared__ float As[8][128], Bs[8][128];
    float acc[8][8];
#pragma unroll
    for (int i = 0; i < 8; i++)
#pragma unroll
        for (int j = 0; j < 8; j++) acc[i][j] = 0.f;

    const float* Ut = eigs + (size_t)b*EROWS*NK + (size_t)(1+NV)*NK;
    const float* hb = h   + (size_t)b*NV*NH;
    int v0 = c*VCHROWS;
    int lr = t >> 5, lc4 = (t & 31) * 4;

    for (int vv = 0; vv < VCHROWS; vv += 8) {
        float4 a  = *(const float4*)(Ut + (size_t)(v0+vv+lr)*NK + lc4);
        float4 bb = *(const float4*)(hb + (size_t)(v0+vv+lr)*NH + lc4);
        *(float4*)&As[lr][lc4] = a;
        *(float4*)&Bs[lr][lc4] = bb;
        __syncthreads();
#pragma unroll
        for (int kk = 0; kk < 8; kk++) {
            float av[8], bv[8];
            *(float4*)&av[0] = *(const float4*)&As[kk][ty*8];
            *(float4*)&av[4] = *(const float4*)&As[kk][ty*8+4];
            *(float4*)&bv[0] = *(const float4*)&Bs[kk][tx*8];
            *(float4*)&bv[4] = *(const float4*)&Bs[kk][tx*8+4];
#pragma unroll
            for (int i = 0; i < 8; i++)
#pragma unroll
                for (int j = 0; j < 8; j++) acc[i][j] = fmaf(av[i], bv[j], acc[i][j]);
        }
        __syncthreads();
    }
    float* dst = g_part + (size_t)(b*VCH + c)*NK*NH;
#pragma unroll
    for (int i = 0; i < 8; i++)
#pragma unroll
        for (int j = 0; j < 8; j++)
            dst[(size_t)(ty*8+i)*NH + tx*8+j] = acc[i][j];
}

// ---------------- modulate ----------------
__global__ void k_modulate(const float* __restrict__ eigs,
                           const float* __restrict__ ptime,
                           const float* __restrict__ bem_,
                           const float* __restrict__ bes_) {
    int k = blockIdx.x, b = blockIdx.y, hh = threadIdx.x;
    float s = 0.f;
#pragma unroll 8
    for (int c = 0; c < VCH; c++)
        s += g_part[((size_t)(b*VCH + c)*NK + k)*NH + hh];
    float ev   = eigs[(size_t)b*EROWS*NK + k];
    float time = fmaxf(ptime[hh], 1e-6f);
    float bem  = fminf(fmaxf(bem_[hh], 1e-6f), 0.3f);
    float bes  = fmaxf(bes_[hh], 0.05f);
    float d    = bem - ev;
    float band = expf(-d*d / (2.f*bes*bes));
    float prop = expf(-ev*time);
    float val  = band * prop * s;
    int o = (b*NH + hh)*NK + k;
    splitf(val, g_mTh[o], g_mTl[o]);
}

// ---------------- spectral up ----------------
__global__ __launch_bounds__(256) void k_specup_c() {
    int h0 = blockIdx.x*64, v0 = blockIdx.y*128, b = blockIdx.z;
    extern __shared__ __align__(256) char smem[];
    uint32_t sb = s2u(smem);
    int t = threadIdx.x, w = t>>5, lane = t&31;
    int m0w = (w&3)*32, n0w = (w>>2)*32;
    int gid = lane>>2, tig = lane&3;

    cpa_tile256(sb+0,     g_Uh  + ((size_t)b*NV + v0)*128, 128, 128, t, 256);
    cpa_tile256(sb+32768, g_Ul  + ((size_t)b*NV + v0)*128, 128, 128, t, 256);
    cpa_tile256(sb+65536, g_mTh + (size_t)(b*NH + h0)*128,  64, 128, t, 256);
    cpa_tile256(sb+81920, g_mTl + (size_t)(b*NH + h0)*128,  64, 128, t, 256);
    CP_COMMIT(); CP_WAIT0(); __syncthreads();

    float acc[2][4][4];
#pragma unroll
    for (int i=0;i<2;i++)
#pragma unroll
        for (int j=0;j<4;j++)
#pragma unroll
            for (int q=0;q<4;q++) acc[i][j][q]=0.f;

#pragma unroll
    for (int ks = 0; ks < 8; ks++) {
        uint32_t ah[2][4], al[2][4];
#pragma unroll
        for (int mf=0; mf<2; mf++){
            ldA256(ah[mf], sb+0,     m0w+mf*16, ks, lane);
            ldA256(al[mf], sb+32768, m0w+mf*16, ks, lane);
        }
#pragma unroll
        for (int nf=0; nf<4; nf++){
            uint32_t bh[2], bl[2];
            ldB256(bh, sb+65536, n0w+nf*8, ks, lane);
            ldB256(bl, sb+81920, n0w+nf*8, ks, lane);
#pragma unroll
            for (int mf=0; mf<2; mf++){
                mmab(acc[mf][nf], ah[mf], bh);
                mmab(acc[mf][nf], ah[mf], bl);
                mmab(acc[mf][nf], al[mf], bh);
            }
        }
    }
#pragma unroll
    for (int mf=0; mf<2; mf++)
#pragma unroll
        for (int nf=0; nf<4; nf++){
            int r = m0w + mf*16 + gid, c = h0 + n0w + nf*8 + tig*2;
            size_t o0 = ((size_t)b*NV + v0 + r)*128 + c;
            size_t o1 = o0 + (size_t)8*128;
            st_pair(g_hph+o0, g_hpl+o0, acc[mf][nf][0], acc[mf][nf][1]);
            st_pair(g_hph+o1, g_hpl+o1, acc[mf][nf][2], acc[mf][nf][3]);
        }
}

// ---------------- CSR build ----------------
__global__ void k_count(const int* __restrict__ gidx) {
    int i = blockIdx.x*blockDim.x + threadIdx.x;
    if (i >= NB*NNZV) return;
    int b = i / NNZV, n = i % NNZV;
    int row = gidx[(size_t)(b*2)*NNZV + n];
    atomicAdd(&g_cnt[b*NV + row], 1);
}
__global__ void k_scan() {
    int b = blockIdx.x, t = threadIdx.x;
    __shared__ int sm[1024];
    int loc[8]; int s = 0;
#pragma unroll
    for (int w = 0; w < 8; w++) { loc[w] = s; s += g_cnt[b*NV + t*8 + w]; }
    sm[t] = s; __syncthreads();
    for (int off = 1; off < 1024; off <<= 1) {
        int v = (t >= off) ? sm[t-off] : 0;
        __syncthreads();
        sm[t] += v;
        __syncthreads();
    }
    int base = (t > 0) ? sm[t-1] : 0;
#pragma unroll
    for (int w = 0; w < 8; w++) g_off[b*NV + t*8 + w] = base + loc[w];
}
__global__ void k_scatter(const int* __restrict__ gidx) {
    int i = blockIdx.x*blockDim.x + threadIdx.x;
    if (i >= NB*NNZV) return;
    int b = i / NNZV, n = i % NNZV;
    int row = gidx[(size_t)(b*2)*NNZV + n];
    int pos = g_off[b*NV + row] + atomicAdd(&g_cur[b*NV + row], 1);
    g_perm[(size_t)b*NNZV + pos] = n;
}

// ---------------- gather ----------------
__global__ __launch_bounds__(256) void k_gather(const float* __restrict__ h,
                                                const float* __restrict__ gvals,
                                                const int* __restrict__ gidx) {
    int warp = (blockIdx.x*blockDim.x + threadIdx.x) >> 5;
    int lane = threadIdx.x & 31;
    if (warp >= BV) return;
    int b = warp / NV, v = warp % NV;
    int start = g_off[b*NV + v];
    int end   = (v == NV-1) ? NNZV : g_off[b*NV + v + 1];
    float4 ax = {0.f,0.f,0.f,0.f}, ay = {0.f,0.f,0.f,0.f};
    const float* hb   = h + (size_t)b*NV*NH;
    const int*   colp = gidx  + (size_t)(b*2+1)*NNZV;
    const float* vx   = gvals + (size_t)(b*2)*NNZV;
    const float* vy   = vx + NNZV;
    const int*   perm = g_perm + (size_t)b*NNZV;
    for (int e = start; e < end; e++) {
        int n = perm[e];
        int col = colp[n];
        float sx = vx[n], sy = vy[n];
        float4 hv = *(const float4*)(hb + (size_t)col*NH + lane*4);
        ax.x = fmaf(sx, hv.x, ax.x); ax.y = fmaf(sx, hv.y, ax.y);
        ax.z = fmaf(sx, hv.z, ax.z); ax.w = fmaf(sx, hv.w, ax.w);
        ay.x = fmaf(sy, hv.x, ay.x); ay.y = fmaf(sy, hv.y, ay.y);
        ay.z = fmaf(sy, hv.z, ay.z); ay.w = fmaf(sy, hv.w, ay.w);
    }
    ax.x = fminf(fmaxf(ax.x,-1.f),1.f); ax.y = fminf(fmaxf(ax.y,-1.f),1.f);
    ax.z = fminf(fmaxf(ax.z,-1.f),1.f); ax.w = fminf(fmaxf(ax.w,-1.f),1.f);
    ay.x = fminf(fmaxf(ay.x,-1.f),1.f); ay.y = fminf(fmaxf(ay.y,-1.f),1.f);
    ay.z = fminf(fmaxf(ay.z,-1.f),1.f); ay.w = fminf(fmaxf(ay.w,-1.f),1.f);
    size_t o = (size_t)(b*NV + v)*NH + lane*4;
    st_pair(g_gxh+o,   g_gxl+o,   ax.x, ax.y);
    st_pair(g_gxh+o+2, g_gxl+o+2, ax.z, ax.w);
    st_pair(g_gyh+o,   g_gyl+o,   ay.x, ay.y);
    st_pair(g_gyh+o+2, g_gyl+o+2, ay.z, ay.w);
}

// ---------------- gradcomb: 4 fused GEMMs, full-K, 512 thr, 192KB smem ----------------
__global__ __launch_bounds__(512) void k_gradcomb_c(const float* __restrict__ gbasis,
                                                    const float* __restrict__ vnorm) {
    size_t r0 = (size_t)blockIdx.x * 64;
    extern __shared__ __align__(256) char smem[];
    uint32_t sb = s2u(smem);
    __shared__ float c_s[64];
    int t = threadIdx.x, w = t>>5, lane = t&31;
    int m0w = (w&3)*16, n0w = (w>>2)*32;
    int gid = lane>>2, tig = lane&3;

    if (t < 64) {
        const float* gb = gbasis + (r0 + t)*6;
        const float* vn = vnorm  + (r0 + t)*3;
        float bx0 = gb[0], bx1 = gb[1], bx2 = gb[2];
        float by0 = gb[3], by1 = gb[4], by2 = gb[5];
        float cx = bx1*by2 - bx2*by1;
        float cy = bx2*by0 - bx0*by2;
        float cz = bx0*by1 - bx1*by0;
        c_s[t] = cx*vn[0] + cy*vn[1] + cz*vn[2];
    }
    cpa_tile256(sb+0,      g_gxh + r0*128, 64, 128, t, 512);
    cpa_tile256(sb+16384,  g_gxl + r0*128, 64, 128, t, 512);
    cpa_tile256(sb+32768,  g_gyh + r0*128, 64, 128, t, 512);
    cpa_tile256(sb+49152,  g_gyl + r0*128, 64, 128, t, 512);
    cpa_tile256(sb+65536,  g_Wgh,  128, 128, t, 512);
    cpa_tile256(sb+98304,  g_Wgl,  128, 128, t, 512);
    cpa_tile256(sb+131072, g_Wg2h, 128, 128, t, 512);
    cpa_tile256(sb+163840, g_Wg2l, 128, 128, t, 512);
    CP_COMMIT(); CP_WAIT0(); __syncthreads();

    float acc[4][4][4];
#pragma unroll
    for (int g=0;g<4;g++)
#pragma unroll
        for (int j=0;j<4;j++)
#pragma unroll
            for (int q=0;q<4;q++) acc[g][j][q]=0.f;

#pragma unroll
    for (int ks = 0; ks < 8; ks++) {
        uint32_t axh[4], axl[4], ayh[4], ayl[4];
        ldA256(axh, sb+0,     m0w, ks, lane);
        ldA256(axl, sb+16384, m0w, ks, lane);
        ldA256(ayh, sb+32768, m0w, ks, lane);
        ldA256(ayl, sb+49152, m0w, ks, lane);
#pragma unroll
        for (int nf = 0; nf < 4; nf++) {
            uint32_t wgh[2], wgl[2], w2h[2], w2l[2];
            ldB256(wgh, sb+65536,  n0w+nf*8, ks, lane);
            ldB256(wgl, sb+98304,  n0w+nf*8, ks, lane);
            ldB256(w2h, sb+131072, n0w+nf*8, ks, lane);
            ldB256(w2l, sb+163840, n0w+nf*8, ks, lane);
            mmab(acc[0][nf], axh, wgh); mmab(acc[0][nf], axh, wgl); mmab(acc[0][nf], axl, wgh);
            mmab(acc[1][nf], ayh, w2h); mmab(acc[1][nf], ayh, w2l); mmab(acc[1][nf], ayl, w2h);
            mmab(acc[2][nf], ayh, wgh); mmab(acc[2][nf], ayh, wgl); mmab(acc[2][nf], ayl, wgh);
            mmab(acc[3][nf], axh, w2h); mmab(acc[3][nf], axh, w2l); mmab(acc[3][nf], axl, w2h);
        }
    }
#pragma unroll
    for (int nf = 0; nf < 4; nf++) {
        int r = m0w + gid, c = n0w + nf*8 + tig*2;
        float cs0 = c_s[r], cs1 = c_s[r+8];
        float v00 = (acc[0][nf][0]*acc[1][nf][0] - acc[2][nf][0]*acc[3][nf][0]) * cs0;
        float v01 = (acc[0][nf][1]*acc[1][nf][1] - acc[2][nf][1]*acc[3][nf][1]) * cs0;
        float v10 = (acc[0][nf][2]*acc[1][nf][2] - acc[2][nf][2]*acc[3][nf][2]) * cs1;
        float v11 = (acc[0][nf][3]*acc[1][nf][3] - acc[2][nf][3]*acc[3][nf][3]) * cs1;
        size_t o0 = (r0 + r)*128 + c;
        size_t o1 = o0 + (size_t)8*128;
        st_pair(g_hgh+o0, g_hgl+o0, v00, v01);
        st_pair(g_hgh+o1, g_hgl+o1, v10, v11);
    }
}

// ---------------- MLP1 + fused BN1 column stats ----------------
__global__ __launch_bounds__(256) void k_mlp1_c(const float* __restrict__ b1) {
    int o0 = blockIdx.x * 64;
    size_t r0 = (size_t)blockIdx.y * 128;
    extern __shared__ __align__(256) char smem[];
    uint32_t sb = s2u(smem);
    __shared__ float s_sum[64], s_sq[64];
    int t = threadIdx.x, w = t>>5, lane = t&31;
    int m0w = (w&3)*32, n0w = (w>>2)*32;
    int gid = lane>>2, tig = lane&3;

    if (t < 64) { s_sum[t] = 0.f; s_sq[t] = 0.f; }

    float acc[2][4][4];
#pragma unroll
    for (int i=0;i<2;i++)
#pragma unroll
        for (int j=0;j<4;j++)
#pragma unroll
            for (int q=0;q<4;q++) acc[i][j][q]=0.f;

    auto load_chunk = [&](int c, int buf){
        uint32_t st = sb + buf*49152;
        const __nv_bfloat16 *ah = (c<2) ? g_hh : (c<4) ? g_hph : g_hgh;
        const __nv_bfloat16 *al = (c<2) ? g_hl : (c<4) ? g_hpl : g_hgl;
        int off = (c&1)*64;
        cpa_tile128(st,        ah + r0*128 + off, 128, 128, t, 256);
        cpa_tile128(st+16384,  al + r0*128 + off, 128, 128, t, 256);
        cpa_tile128(st+32768,  g_W1h + (size_t)o0*384 + c*64, 64, 384, t, 256);
        cpa_tile128(st+40960,  g_W1l + (size_t)o0*384 + c*64, 64, 384, t, 256);
        CP_COMMIT();
    };
    load_chunk(0, 0);
    for (int c = 0; c < 6; c++) {
        if (c < 5) load_chunk(c+1, (c+1)&1);
        if (c < 5) { CP_WAIT1(); } else { CP_WAIT0(); }
        __syncthreads();
        uint32_t st = sb + (c&1)*49152;
#pragma unroll
        for (int ks = 0; ks < 4; ks++) {
            uint32_t ah[2][4], al[2][4];
#pragma unroll
            for (int mf=0; mf<2; mf++){
                ldA128(ah[mf], st,       m0w+mf*16, ks, lane);
                ldA128(al[mf], st+16384, m0w+mf*16, ks, lane);
            }
#pragma unroll
            for (int nf=0; nf<4; nf++){
                uint32_t bh[2], bl[2];
                ldB128(bh, st+32768, n0w+nf*8, ks, lane);
                ldB128(bl, st+40960, n0w+nf*8, ks, lane);
#pragma unroll
                for (int mf=0; mf<2; mf++){
                    mmab(acc[mf][nf], ah[mf], bh);
                    mmab(acc[mf][nf], ah[mf], bl);
                    mmab(acc[mf][nf], al[mf], bh);
                }
            }
        }
        __syncthreads();
    }
    float* dst = g_x1 + r0*256 + o0;
#pragma unroll
    for (int mf=0; mf<2; mf++)
#pragma unroll
        for (int nf=0; nf<4; nf++){
            int r = m0w + mf*16 + gid, c = n0w + nf*8 + tig*2;
            float bb0 = b1[o0+c], bb1 = b1[o0+c+1];
            float v00 = acc[mf][nf][0] + bb0, v01 = acc[mf][nf][1] + bb1;
            float v10 = acc[mf][nf][2] + bb0, v11 = acc[mf][nf][3] + bb1;
            float2 lo; lo.x = v00; lo.y = v01;
            float2 hi; hi.x = v10; hi.y = v11;
            *(float2*)(dst + (size_t)r*256 + c)     = lo;
            *(float2*)(dst + (size_t)(r+8)*256 + c) = hi;
            atomicAdd(&s_sum[c],   v00 + v10);
            atomicAdd(&s_sum[c+1], v01 + v11);
            atomicAdd(&s_sq[c],    v00*v00 + v10*v10);
            atomicAdd(&s_sq[c+1],  v01*v01 + v11*v11);
        }
    __syncthreads();
    if (t < 64) {
        atomicAdd(&g_sum1[o0 + t], s_sum[t]);
        atomicAdd(&g_sq1[o0 + t],  s_sq[t]);
    }
}

// ---------------- BN finalize / act split ----------------
__global__ void k_fin1(const float* __restrict__ gamma, const float* __restrict__ beta) {
    int t = threadIdx.x;
    if (t < 256) {
        float mean = g_sum1[t] / (float)BV;
        float var  = g_sq1[t] / (float)BV - mean*mean;
        float inv  = rsqrtf(var + 1e-5f);
        float sc   = gamma[t]*inv;
        g_scale1[t] = sc;
        g_shift1[t] = beta[t] - mean*sc;
    }
}
__global__ void k_actsplit() {
    size_t i = (size_t)blockIdx.x*blockDim.x + threadIdx.x;
    if (i < (size_t)BV*256) {
        int c = (int)(i & 255);
        float v = fmaxf(g_x1[i]*g_scale1[c] + g_shift1[c], 0.f);
        splitf(v, g_a1h[i], g_a1l[i]);
    }
}
__global__ void k_fin2(const float* __restrict__ gamma, const float* __restrict__ beta) {
    int t = threadIdx.x;
    if (t < 128) {
        float mean = g_sum2[t] / (float)BV;
        float var  = g_sq2[t] / (float)BV - mean*mean;
        float inv  = rsqrtf(var + 1e-5f);
        float sc   = gamma[t]*inv;
        g_scale2[t] = sc;
        g_shift2[t] = beta[t] - mean*sc;
    }
}

// ---------------- MLP2 + fused BN2 column stats ----------------
__global__ __launch_bounds__(256) void k_mlp2_c(const float* __restrict__ b2) {
    int h0 = blockIdx.x * 64;
    size_t r0 = (size_t)blockIdx.y * 128;
    extern __shared__ __align__(256) char smem[];
    uint32_t sb = s2u(smem);
    __shared__ float s_sum[64], s_sq[64];
    int t = threadIdx.x, w = t>>5, lane = t&31;
    int m0w = (w&3)*32, n0w = (w>>2)*32;
    int gid = lane>>2, tig = lane&3;

    if (t < 64) { s_sum[t] = 0.f; s_sq[t] = 0.f; }

    float acc[2][4][4];
#pragma unroll
    for (int i=0;i<2;i++)
#pragma unroll
        for (int j=0;j<4;j++)
#pragma unroll
            for (int q=0;q<4;q++) acc[i][j][q]=0.f;

    auto load_chunk = [&](int c, int buf){
        uint32_t st = sb + buf*49152;
        cpa_tile128(st,        g_a1h + r0*256 + c*64, 128, 256, t, 256);
        cpa_tile128(st+16384,  g_a1l + r0*256 + c*64, 128, 256, t, 256);
        cpa_tile128(st+32768,  g_W2h + (size_t)h0*256 + c*64, 64, 256, t, 256);
        cpa_tile128(st+40960,  g_W2l + (size_t)h0*256 + c*64, 64, 256, t, 256);
        CP_COMMIT();
    };
    load_chunk(0, 0);
    for (int c = 0; c < 4; c++) {
        if (c < 3) load_chunk(c+1, (c+1)&1);
        if (c < 3) { CP_WAIT1(); } else { CP_WAIT0(); }
        __syncthreads();
        uint32_t st = sb + (c&1)*49152;
#pragma unroll
        for (int ks = 0; ks < 4; ks++) {
            uint32_t ah[2][4], al[2][4];
#pragma unroll
            for (int mf=0; mf<2; mf++){
                ldA128(ah[mf], st,       m0w+mf*16, ks, lane);
                ldA128(al[mf], st+16384, m0w+mf*16, ks, lane);
            }
#pragma unroll
            for (int nf=0; nf<4; nf++){
                uint32_t bh[2], bl[2];
                ldB128(bh, st+32768, n0w+nf*8, ks, lane);
                ldB128(bl, st+40960, n0w+nf*8, ks, lane);
#pragma unroll
                for (int mf=0; mf<2; mf++){
                    mmab(acc[mf][nf], ah[mf], bh);
                    mmab(acc[mf][nf], ah[mf], bl);
                    mmab(acc[mf][nf], al[mf], bh);
                }
            }
        }
        __syncthreads();
    }
    float* dst = g_x2 + r0*128 + h0;
#pragma unroll
    for (int mf=0; mf<2; mf++)
#pragma unroll
        for (int nf=0; nf<4; nf++){
            int r = m0w + mf*16 + gid, c = n0w + nf*8 + tig*2;
            float bb0 = b2[h0+c], bb1 = b2[h0+c+1];
            float v00 = acc[mf][nf][0] + bb0, v01 = acc[mf][nf][1] + bb1;
            float v10 = acc[mf][nf][2] + bb0, v11 = acc[mf][nf][3] + bb1;
            float2 lo; lo.x = v00; lo.y = v01;
            float2 hi; hi.x = v10; hi.y = v11;
            *(float2*)(dst + (size_t)r*128 + c)     = lo;
            *(float2*)(dst + (size_t)(r+8)*128 + c) = hi;
            atomicAdd(&s_sum[c],   v00 + v10);
            atomicAdd(&s_sum[c+1], v01 + v11);
            atomicAdd(&s_sq[c],    v00*v00 + v10*v10);
            atomicAdd(&s_sq[c+1],  v01*v01 + v11*v11);
        }
    __syncthreads();
    if (t < 64) {
        atomicAdd(&g_sum2[h0 + t], s_sum[t]);
        atomicAdd(&g_sq2[h0 + t],  s_sq[t]);
    }
}

// ---------------- final: out = h + bn2(x2) ----------------
__global__ void k_final(const float* __restrict__ h, float* __restrict__ out) {
    size_t i = (size_t)blockIdx.x*blockDim.x + threadIdx.x;
    if (i < (size_t)BV*NH) {
        int c = (int)(i & 127);
        out[i] = h[i] + g_scale2[c]*g_x2[i] + g_shift2[c];
    }
}

// ---------------- launch ----------------
extern "C" void kernel_launch(void* const* d_in, const int* in_sizes, int n_in,
                              void* d_out, int out_size) {
    const float* h      = (const float*)d_in[0];
    const float* eigs   = (const float*)d_in[1];
    const float* gvals  = (const float*)d_in[2];
    const int*   gidx   = (const int*)  d_in[3];
    const float* gbasis = (const float*)d_in[4];
    const float* vnorm  = (const float*)d_in[5];
    const float* ptime  = (const float*)d_in[6];
    const float* bem    = (const float*)d_in[7];
    const float* bes    = (const float*)d_in[8];
    const float* Wg     = (const float*)d_in[9];
    const float* Wg2    = (const float*)d_in[10];
    const float* W1     = (const float*)d_in[11];
    const float* b1     = (const float*)d_in[12];
    const float* gamma1 = (const float*)d_in[13];
    const float* beta1  = (const float*)d_in[14];
    const float* W2     = (const float*)d_in[15];
    const float* b2     = (const float*)d_in[16];
    const float* gamma2 = (const float*)d_in[17];
    const float* beta2  = (const float*)d_in[18];
    float* out = (float*)d_out;

    const int SM_SPECUP = 98304;
    const int SM_GRAD   = 196608;
    const int SM_MLP    = 98304;
    cudaFuncSetAttribute(k_specup_c,   cudaFuncAttributeMaxDynamicSharedMemorySize, SM_SPECUP);
    cudaFuncSetAttribute(k_gradcomb_c, cudaFuncAttributeMaxDynamicSharedMemorySize, SM_GRAD);
    cudaFuncSetAttribute(k_mlp1_c,     cudaFuncAttributeMaxDynamicSharedMemorySize, SM_MLP);
    cudaFuncSetAttribute(k_mlp2_c,     cudaFuncAttributeMaxDynamicSharedMemorySize, SM_MLP);

    k_zero<<<256, 256>>>();
    k_prep1<<<(163840 + 2*NVK + 255)/256, 256>>>(W1, W2, Wg, Wg2, eigs, h);
    k_specdown<<<dim3(VCH, NB), 256>>>(eigs, h);
    k_modulate<<<dim3(NK, NB), NH>>>(eigs, ptime, bem, bes);
    k_specup_c<<<dim3(2, NV/128, NB), 256, SM_SPECUP>>>();
    k_count<<<(NB*NNZV + 255)/256, 256>>>(gidx);
    k_scan<<<NB, 1024>>>();
    k_scatter<<<(NB*NNZV + 255)/256, 256>>>(gidx);
    k_gather<<<BV/8, 256>>>(h, gvals, gidx);
    k_gradcomb_c<<<BV/64, 512, SM_GRAD>>>(gbasis, vnorm);
    k_mlp1_c<<<dim3(4, BV/128), 256, SM_MLP>>>(b1);
    k_fin1<<<1, 256>>>(gamma1, beta1);
    k_actsplit<<<(int)(((size_t)BV*256 + 255)/256), 256>>>();
    k_mlp2_c<<<dim3(2, BV/128), 256, SM_MLP>>>(b2);
    k_fin2<<<1, 128>>>(gamma2, beta2);
    k_final<<<(int)(((size_t)BV*NH + 255)/256), 256>>>(h, out);
}

// round 10
// speedup vs baseline: 1.2901x; 1.2901x over previous
#include <cuda_runtime.h>
#include <cuda_bf16.h>
#include <math.h>
#include <stdint.h>

#define NB 8
#define NV 8192
#define NH 128
#define NK 128
#define NNZV 57344
#define BV (NB*NV)            // 65536
#define EROWS (1+2*NV)        // 16385
#define VCH 32
#define VCHROWS 256
#define NVK 8388608           // NB*NV*NK

// ---------------- fp32 scratch ----------------
__device__ float g_part[(size_t)NB*VCH*NK*NH];   // 16.8MB
__device__ float g_x1[(size_t)BV*256];           // 67MB
__device__ float g_x2[(size_t)BV*128];           // 33.5MB

// ---------------- bf16 hi/lo operand arrays ----------------
__device__ __align__(256) __nv_bfloat16 g_mTh[NB*NH*NK], g_mTl[NB*NH*NK];
__device__ __align__(256) __nv_bfloat16 g_Uh[NVK],  g_Ul[NVK];
__device__ __align__(256) __nv_bfloat16 g_hh[NVK],  g_hl[NVK];
__device__ __align__(256) __nv_bfloat16 g_uth[NVK], g_utl[NVK];   // Ut^T: [b][k][v]
__device__ __align__(256) __nv_bfloat16 g_hth[NVK], g_htl[NVK];   // h^T:  [b][h][v]
__device__ __align__(256) __nv_bfloat16 g_hph[NVK], g_hpl[NVK];
__device__ __align__(256) __nv_bfloat16 g_hgh[NVK], g_hgl[NVK];
__device__ __align__(256) __nv_bfloat16 g_gxh[NVK], g_gxl[NVK];
__device__ __align__(256) __nv_bfloat16 g_gyh[NVK], g_gyl[NVK];
__device__ __align__(256) __nv_bfloat16 g_a1h[(size_t)BV*256], g_a1l[(size_t)BV*256];
__device__ __align__(256) __nv_bfloat16 g_W1h[256*384], g_W1l[256*384];
__device__ __align__(256) __nv_bfloat16 g_W2h[128*256], g_W2l[128*256];
__device__ __align__(256) __nv_bfloat16 g_Wgh[128*128], g_Wgl[128*128];
__device__ __align__(256) __nv_bfloat16 g_Wg2h[128*128], g_Wg2l[128*128];

__device__ float g_sum1[256], g_sq1[256], g_scale1[256], g_shift1[256];
__device__ float g_sum2[128], g_sq2[128], g_scale2[128], g_shift2[128];
__device__ int   g_cnt[BV], g_cur[BV], g_off[BV];
__device__ int   g_perm[NB*NNZV];

// ---------------- PTX helpers ----------------
__device__ __forceinline__ uint32_t s2u(const void* p){
    uint32_t a;
    asm("{ .reg .u64 t; cvta.to.shared.u64 t, %1; cvt.u32.u64 %0, t; }" : "=r"(a) : "l"(p));
    return a;
}
#define CP_ASYNC16(dst, src) asm volatile("cp.async.cg.shared.global [%0], [%1], 16;" :: "r"(dst), "l"(src))
#define CP_COMMIT()          asm volatile("cp.async.commit_group;" ::: "memory")
#define CP_WAIT0()           asm volatile("cp.async.wait_group 0;" ::: "memory")
#define CP_WAIT1()           asm volatile("cp.async.wait_group 1;" ::: "memory")

__device__ __forceinline__ void ldmx4(uint32_t* r, uint32_t a){
    asm volatile("ldmatrix.sync.aligned.m8n8.x4.shared.b16 {%0,%1,%2,%3}, [%4];"
        : "=r"(r[0]),"=r"(r[1]),"=r"(r[2]),"=r"(r[3]) : "r"(a));
}
__device__ __forceinline__ void ldmx2(uint32_t* r, uint32_t a){
    asm volatile("ldmatrix.sync.aligned.m8n8.x2.shared.b16 {%0,%1}, [%2];"
        : "=r"(r[0]),"=r"(r[1]) : "r"(a));
}
__device__ __forceinline__ void mmab(float* c, const uint32_t* a, const uint32_t* b){
    asm volatile("mma.sync.aligned.m16n8k16.row.col.f32.bf16.bf16.f32 "
        "{%0,%1,%2,%3}, {%4,%5,%6,%7}, {%8,%9}, {%0,%1,%2,%3};"
        : "+f"(c[0]),"+f"(c[1]),"+f"(c[2]),"+f"(c[3])
        : "r"(a[0]),"r"(a[1]),"r"(a[2]),"r"(a[3]), "r"(b[0]),"r"(b[1]));
}

// ---------------- cp.async tile loaders (chunk-XOR swizzle: cb ^= row&7) ----------------
__device__ __forceinline__ void cpa_tile256(uint32_t sdst, const __nv_bfloat16* g,
                                            int rows, int rowstride, int t, int nthr){
    for (int i = t; i < rows*16; i += nthr){
        int r = i>>4, cb = i&15;
        CP_ASYNC16(sdst + r*256 + ((cb ^ (r&7))*16), g + (size_t)r*rowstride + cb*8);
    }
}
__device__ __forceinline__ void cpa_tile128(uint32_t sdst, const __nv_bfloat16* g,
                                            int rows, int rowstride, int t, int nthr){
    for (int i = t; i < rows*8; i += nthr){
        int r = i>>3, cb = i&7;
        CP_ASYNC16(sdst + r*128 + ((cb ^ (r&7))*16), g + (size_t)r*rowstride + cb*8);
    }
}
__device__ __forceinline__ void ldA256(uint32_t* fr, uint32_t base, int m0, int ks, int lane){
    int r = m0 + (lane&15), cb = ks*2 + (lane>>4);
    ldmx4(fr, base + r*256 + ((cb ^ (r&7))*16));
}
__device__ __forceinline__ void ldB256(uint32_t* fr, uint32_t base, int n0, int ks, int lane){
    int r = n0 + (lane&7), cb = ks*2 + ((lane>>3)&1);
    ldmx2(fr, base + r*256 + ((cb ^ (r&7))*16));
}
__device__ __forceinline__ void ldA128(uint32_t* fr, uint32_t base, int m0, int ks, int lane){
    int r = m0 + (lane&15), cb = ks*2 + (lane>>4);
    ldmx4(fr, base + r*128 + ((cb ^ (r&7))*16));
}
__device__ __forceinline__ void ldB128(uint32_t* fr, uint32_t base, int n0, int ks, int lane){
    int r = n0 + (lane&7), cb = ks*2 + ((lane>>3)&1);
    ldmx2(fr, base + r*128 + ((cb ^ (r&7))*16));
}

// ---------------- bf16 split ----------------
__device__ __forceinline__ void splitf(float v, __nv_bfloat16 &hi, __nv_bfloat16 &lo){
    hi = __float2bfloat16(v);
    lo = __float2bfloat16(v - __bfloat162float(hi));
}
__device__ __forceinline__ void st_pair(__nv_bfloat16* ph, __nv_bfloat16* pl, float a, float b){
    __nv_bfloat16 ha,la,hb,lb; splitf(a,ha,la); splitf(b,hb,lb);
    __nv_bfloat162 H; H.x=ha; H.y=hb;
    __nv_bfloat162 L; L.x=la; L.y=lb;
    *(__nv_bfloat162*)ph = H;
    *(__nv_bfloat162*)pl = L;
}

// ---------------- zero small state ----------------
__global__ void k_zero() {
    int i = blockIdx.x*blockDim.x + threadIdx.x;
    if (i < BV) { g_cnt[i] = 0; g_cur[i] = 0; }
    if (i < 256) { g_sum1[i] = 0.f; g_sq1[i] = 0.f; }
    if (i < 128) { g_sum2[i] = 0.f; g_sq2[i] = 0.f; }
}

// ---------------- prep: split W1,W2,Wg,Wg2,U,h to bf16 hi/lo ----------------
__global__ void k_prep1(const float* __restrict__ W1, const float* __restrict__ W2,
                        const float* __restrict__ Wg, const float* __restrict__ Wg2,
                        const float* __restrict__ eigs, const float* __restrict__ h) {
    int i = blockIdx.x*blockDim.x + threadIdx.x;
    if (i < 98304)        { splitf(W1[i],  g_W1h[i],  g_W1l[i]); }
    else if (i < 131072)  { int j = i - 98304;  splitf(W2[j],  g_W2h[j],  g_W2l[j]); }
    else if (i < 147456)  { int j = i - 131072; splitf(Wg[j],  g_Wgh[j],  g_Wgl[j]); }
    else if (i < 163840)  { int j = i - 147456; splitf(Wg2[j], g_Wg2h[j], g_Wg2l[j]); }
    else if (i < 163840 + NVK) {
        int j = i - 163840;
        int b = j >> 20, r = j & 1048575;       // NV*NK = 2^20
        float v = eigs[(size_t)b*EROWS*NK + NK + r];   // U rows start at 1
        splitf(v, g_Uh[j], g_Ul[j]);
    } else if (i < 163840 + 2*NVK) {
        int j = i - 163840 - NVK;
        splitf(h[j], g_hh[j], g_hl[j]);
    }
}

// ---------------- transpose: Ut[v][k] -> uth/utl [b][k][v]; h[v][c] -> hth/htl [b][c][v] ----------------
__global__ void k_transpose(const float* __restrict__ eigs, const float* __restrict__ h) {
    __shared__ float tile[32][33];
    int b = blockIdx.z;
    int src = blockIdx.y >> 2;          // 0 = Ut, 1 = h
    int kb = (blockIdx.y & 3) * 32;     // column block
    int vb = blockIdx.x * 32;
    int tx = threadIdx.x, ty = threadIdx.y;
    const float* S = src ? (h + (size_t)b*NV*NH)
                         : (eigs + (size_t)b*EROWS*NK + (size_t)(1+NV)*NK);
    for (int r = ty; r < 32; r += 8)
        tile[r][tx] = S[(size_t)(vb+r)*NK + kb + tx];
    __syncthreads();
    __nv_bfloat16* Dh = src ? g_hth : g_uth;
    __nv_bfloat16* Dl = src ? g_htl : g_utl;
    for (int r = ty; r < 32; r += 8) {
        __nv_bfloat16 hi, lo;
        splitf(tile[tx][r], hi, lo);
        size_t o = ((size_t)b*NK + kb + r)*NV + vb + tx;
        Dh[o] = hi; Dl[o] = lo;
    }
}

// ---------------- specdown (MMA): part[k,h] = sum_v UtT[k,v]*hT[h,v] ----------------
// per CTA: b, chunk c (256 v); K-chunks of 64, double buffered; out 128x128 fp32 -> g_part
__global__ __launch_bounds__(256) void k_sdmma() {
    int c = blockIdx.x, b = blockIdx.y;
    int v0 = c * VCHROWS;
    extern __shared__ __align__(256) char smem[];
    uint32_t sb = s2u(smem);
    int t = threadIdx.x, w = t>>5, lane = t&31;
    int m0w = (w&3)*32, n0w = (w>>2)*64;
    int gid = lane>>2, tig = lane&3;

    float acc[2][8][4];
#pragma unroll
    for (int i=0;i<2;i++)
#pragma unroll
        for (int j=0;j<8;j++)
#pragma unroll
            for (int q=0;q<4;q++) acc[i][j][q]=0.f;

    auto load_chunk = [&](int ch, int buf){
        uint32_t st = sb + buf*65536;
        size_t abase = (size_t)b*NK*NV + v0 + ch*64;
        size_t bbase = (size_t)b*NH*NV + v0 + ch*64;
        cpa_tile128(st,        g_uth + abase, 128, NV, t, 256);
        cpa_tile128(st+16384,  g_utl + abase, 128, NV, t, 256);
        cpa_tile128(st+32768,  g_hth + bbase, 128, NV, t, 256);
        cpa_tile128(st+49152,  g_htl + bbase, 128, NV, t, 256);
        CP_COMMIT();
    };
    load_chunk(0, 0);
    for (int ch = 0; ch < 4; ch++) {
        if (ch < 3) load_chunk(ch+1, (ch+1)&1);
        if (ch < 3) { CP_WAIT1(); } else { CP_WAIT0(); }
        __syncthreads();
        uint32_t st = sb + (ch&1)*65536;
#pragma unroll
        for (int ks = 0; ks < 4; ks++) {
            uint32_t ah[2][4], al[2][4];
#pragma unroll
            for (int mf=0; mf<2; mf++){
                ldA128(ah[mf], st,       m0w+mf*16, ks, lane);
                ldA128(al[mf], st+16384, m0w+mf*16, ks, lane);
            }
#pragma unroll
            for (int nf=0; nf<8; nf++){
                uint32_t bh[2], bl[2];
                ldB128(bh, st+32768, n0w+nf*8, ks, lane);
                ldB128(bl, st+49152, n0w+nf*8, ks, lane);
#pragma unroll
                for (int mf=0; mf<2; mf++){
                    mmab(acc[mf][nf], ah[mf], bh);
                    mmab(acc[mf][nf], ah[mf], bl);
                    mmab(acc[mf][nf], al[mf], bh);
                }
            }
        }
        __syncthreads();
    }
    float* dst = g_part + (size_t)(b*VCH + c)*NK*NH;
#pragma unroll
    for (int mf=0; mf<2; mf++)
#pragma unroll
        for (int nf=0; nf<8; nf++){
            int r = m0w + mf*16 + gid, cc = n0w + nf*8 + tig*2;
            float2 lo; lo.x = acc[mf][nf][0]; lo.y = acc[mf][nf][1];
            float2 hi; hi.x = acc[mf][nf][2]; hi.y = acc[mf][nf][3];
            *(float2*)(dst + (size_t)r*NH + cc)     = lo;
            *(float2*)(dst + (size_t)(r+8)*NH + cc) = hi;
        }
}

// ---------------- modulate ----------------
__global__ void k_modulate(const float* __restrict__ eigs,
                           const float* __restrict__ ptime,
                           const float* __restrict__ bem_,
                           const float* __restrict__ bes_) {
    int k = blockIdx.x, b = blockIdx.y, hh = threadIdx.x;
    float s = 0.f;
#pragma unroll 8
    for (int c = 0; c < VCH; c++)
        s += g_part[((size_t)(b*VCH + c)*NK + k)*NH + hh];
    float ev   = eigs[(size_t)b*EROWS*NK + k];
    float time = fmaxf(ptime[hh], 1e-6f);
    float bem  = fminf(fmaxf(bem_[hh], 1e-6f), 0.3f);
    float bes  = fmaxf(bes_[hh], 0.05f);
    float d    = bem - ev;
    float band = expf(-d*d / (2.f*bes*bes));
    float prop = expf(-ev*time);
    float val  = band * prop * s;
    int o = (b*NH + hh)*NK + k;
    splitf(val, g_mTh[o], g_mTl[o]);
}

// ---------------- spectral up ----------------
__global__ __launch_bounds__(256) void k_specup_c() {
    int h0 = blockIdx.x*64, v0 = blockIdx.y*128, b = blockIdx.z;
    extern __shared__ __align__(256) char smem[];
    uint32_t sb = s2u(smem);
    int t = threadIdx.x, w = t>>5, lane = t&31;
    int m0w = (w&3)*32, n0w = (w>>2)*32;
    int gid = lane>>2, tig = lane&3;

    cpa_tile256(sb+0,     g_Uh  + ((size_t)b*NV + v0)*128, 128, 128, t, 256);
    cpa_tile256(sb+32768, g_Ul  + ((size_t)b*NV + v0)*128, 128, 128, t, 256);
    cpa_tile256(sb+65536, g_mTh + (size_t)(b*NH + h0)*128,  64, 128, t, 256);
    cpa_tile256(sb+81920, g_mTl + (size_t)(b*NH + h0)*128,  64, 128, t, 256);
    CP_COMMIT(); CP_WAIT0(); __syncthreads();

    float acc[2][4][4];
#pragma unroll
    for (int i=0;i<2;i++)
#pragma unroll
        for (int j=0;j<4;j++)
#pragma unroll
            for (int q=0;q<4;q++) acc[i][j][q]=0.f;

#pragma unroll
    for (int ks = 0; ks < 8; ks++) {
        uint32_t ah[2][4], al[2][4];
#pragma unroll
        for (int mf=0; mf<2; mf++){
            ldA256(ah[mf], sb+0,     m0w+mf*16, ks, lane);
            ldA256(al[mf], sb+32768, m0w+mf*16, ks, lane);
        }
#pragma unroll
        for (int nf=0; nf<4; nf++){
            uint32_t bh[2], bl[2];
            ldB256(bh, sb+65536, n0w+nf*8, ks, lane);
            ldB256(bl, sb+81920, n0w+nf*8, ks, lane);
#pragma unroll
            for (int mf=0; mf<2; mf++){
                mmab(acc[mf][nf], ah[mf], bh);
                mmab(acc[mf][nf], ah[mf], bl);
                mmab(acc[mf][nf], al[mf], bh);
            }
        }
    }
#pragma unroll
    for (int mf=0; mf<2; mf++)
#pragma unroll
        for (int nf=0; nf<4; nf++){
            int r = m0w + mf*16 + gid, c = h0 + n0w + nf*8 + tig*2;
            size_t o0 = ((size_t)b*NV + v0 + r)*128 + c;
            size_t o1 = o0 + (size_t)8*128;
            st_pair(g_hph+o0, g_hpl+o0, acc[mf][nf][0], acc[mf][nf][1]);
            st_pair(g_hph+o1, g_hpl+o1, acc[mf][nf][2], acc[mf][nf][3]);
        }
}

// ---------------- CSR build ----------------
__global__ void k_count(const int* __restrict__ gidx) {
    int i = blockIdx.x*blockDim.x + threadIdx.x;
    if (i >= NB*NNZV) return;
    int b = i / NNZV, n = i % NNZV;
    int row = gidx[(size_t)(b*2)*NNZV + n];
    atomicAdd(&g_cnt[b*NV + row], 1);
}
__global__ void k_scan() {
    int b = blockIdx.x, t = threadIdx.x;
    __shared__ int sm[1024];
    int loc[8]; int s = 0;
#pragma unroll
    for (int w = 0; w < 8; w++) { loc[w] = s; s += g_cnt[b*NV + t*8 + w]; }
    sm[t] = s; __syncthreads();
    for (int off = 1; off < 1024; off <<= 1) {
        int v = (t >= off) ? sm[t-off] : 0;
        __syncthreads();
        sm[t] += v;
        __syncthreads();
    }
    int base = (t > 0) ? sm[t-1] : 0;
#pragma unroll
    for (int w = 0; w < 8; w++) g_off[b*NV + t*8 + w] = base + loc[w];
}
__global__ void k_scatter(const int* __restrict__ gidx) {
    int i = blockIdx.x*blockDim.x + threadIdx.x;
    if (i >= NB*NNZV) return;
    int b = i / NNZV, n = i % NNZV;
    int row = gidx[(size_t)(b*2)*NNZV + n];
    int pos = g_off[b*NV + row] + atomicAdd(&g_cur[b*NV + row], 1);
    g_perm[(size_t)b*NNZV + pos] = n;
}

// ---------------- gather ----------------
__global__ __launch_bounds__(256) void k_gather(const float* __restrict__ h,
                                                const float* __restrict__ gvals,
                                                const int* __restrict__ gidx) {
    int warp = (blockIdx.x*blockDim.x + threadIdx.x) >> 5;
    int lane = threadIdx.x & 31;
    if (warp >= BV) return;
    int b = warp / NV, v = warp % NV;
    int start = g_off[b*NV + v];
    int end   = (v == NV-1) ? NNZV : g_off[b*NV + v + 1];
    float4 ax = {0.f,0.f,0.f,0.f}, ay = {0.f,0.f,0.f,0.f};
    const float* hb   = h + (size_t)b*NV*NH;
    const int*   colp = gidx  + (size_t)(b*2+1)*NNZV;
    const float* vx   = gvals + (size_t)(b*2)*NNZV;
    const float* vy   = vx + NNZV;
    const int*   perm = g_perm + (size_t)b*NNZV;
    for (int e = start; e < end; e++) {
        int n = perm[e];
        int col = colp[n];
        float sx = vx[n], sy = vy[n];
        float4 hv = *(const float4*)(hb + (size_t)col*NH + lane*4);
        ax.x = fmaf(sx, hv.x, ax.x); ax.y = fmaf(sx, hv.y, ax.y);
        ax.z = fmaf(sx, hv.z, ax.z); ax.w = fmaf(sx, hv.w, ax.w);
        ay.x = fmaf(sy, hv.x, ay.x); ay.y = fmaf(sy, hv.y, ay.y);
        ay.z = fmaf(sy, hv.z, ay.z); ay.w = fmaf(sy, hv.w, ay.w);
    }
    ax.x = fminf(fmaxf(ax.x,-1.f),1.f); ax.y = fminf(fmaxf(ax.y,-1.f),1.f);
    ax.z = fminf(fmaxf(ax.z,-1.f),1.f); ax.w = fminf(fmaxf(ax.w,-1.f),1.f);
    ay.x = fminf(fmaxf(ay.x,-1.f),1.f); ay.y = fminf(fmaxf(ay.y,-1.f),1.f);
    ay.z = fminf(fmaxf(ay.z,-1.f),1.f); ay.w = fminf(fmaxf(ay.w,-1.f),1.f);
    size_t o = (size_t)(b*NV + v)*NH + lane*4;
    st_pair(g_gxh+o,   g_gxl+o,   ax.x, ax.y);
    st_pair(g_gxh+o+2, g_gxl+o+2, ax.z, ax.w);
    st_pair(g_gyh+o,   g_gyl+o,   ay.x, ay.y);
    st_pair(g_gyh+o+2, g_gyl+o+2, ay.z, ay.w);
}

// ---------------- gradcomb: 4 fused GEMMs, full-K, 512 thr, 192KB smem ----------------
__global__ __launch_bounds__(512) void k_gradcomb_c(const float* __restrict__ gbasis,
                                                    const float* __restrict__ vnorm) {
    size_t r0 = (size_t)blockIdx.x * 64;
    extern __shared__ __align__(256) char smem[];
    uint32_t sb = s2u(smem);
    __shared__ float c_s[64];
    int t = threadIdx.x, w = t>>5, lane = t&31;
    int m0w = (w&3)*16, n0w = (w>>2)*32;
    int gid = lane>>2, tig = lane&3;

    if (t < 64) {
        const float* gb = gbasis + (r0 + t)*6;
        const float* vn = vnorm  + (r0 + t)*3;
        float bx0 = gb[0], bx1 = gb[1], bx2 = gb[2];
        float by0 = gb[3], by1 = gb[4], by2 = gb[5];
        float cx = bx1*by2 - bx2*by1;
        float cy = bx2*by0 - bx0*by2;
        float cz = bx0*by1 - bx1*by0;
        c_s[t] = cx*vn[0] + cy*vn[1] + cz*vn[2];
    }
    cpa_tile256(sb+0,      g_gxh + r0*128, 64, 128, t, 512);
    cpa_tile256(sb+16384,  g_gxl + r0*128, 64, 128, t, 512);
    cpa_tile256(sb+32768,  g_gyh + r0*128, 64, 128, t, 512);
    cpa_tile256(sb+49152,  g_gyl + r0*128, 64, 128, t, 512);
    cpa_tile256(sb+65536,  g_Wgh,  128, 128, t, 512);
    cpa_tile256(sb+98304,  g_Wgl,  128, 128, t, 512);
    cpa_tile256(sb+131072, g_Wg2h, 128, 128, t, 512);
    cpa_tile256(sb+163840, g_Wg2l, 128, 128, t, 512);
    CP_COMMIT(); CP_WAIT0(); __syncthreads();

    float acc[4][4][4];
#pragma unroll
    for (int g=0;g<4;g++)
#pragma unroll
        for (int j=0;j<4;j++)
#pragma unroll
            for (int q=0;q<4;q++) acc[g][j][q]=0.f;

#pragma unroll
    for (int ks = 0; ks < 8; ks++) {
        uint32_t axh[4], axl[4], ayh[4], ayl[4];
        ldA256(axh, sb+0,     m0w, ks, lane);
        ldA256(axl, sb+16384, m0w, ks, lane);
        ldA256(ayh, sb+32768, m0w, ks, lane);
        ldA256(ayl, sb+49152, m0w, ks, lane);
#pragma unroll
        for (int nf = 0; nf < 4; nf++) {
            uint32_t wgh[2], wgl[2], w2h[2], w2l[2];
            ldB256(wgh, sb+65536,  n0w+nf*8, ks, lane);
            ldB256(wgl, sb+98304,  n0w+nf*8, ks, lane);
            ldB256(w2h, sb+131072, n0w+nf*8, ks, lane);
            ldB256(w2l, sb+163840, n0w+nf*8, ks, lane);
            mmab(acc[0][nf], axh, wgh); mmab(acc[0][nf], axh, wgl); mmab(acc[0][nf], axl, wgh);
            mmab(acc[1][nf], ayh, w2h); mmab(acc[1][nf], ayh, w2l); mmab(acc[1][nf], ayl, w2h);
            mmab(acc[2][nf], ayh, wgh); mmab(acc[2][nf], ayh, wgl); mmab(acc[2][nf], ayl, wgh);
            mmab(acc[3][nf], axh, w2h); mmab(acc[3][nf], axh, w2l); mmab(acc[3][nf], axl, w2h);
        }
    }
#pragma unroll
    for (int nf = 0; nf < 4; nf++) {
        int r = m0w + gid, c = n0w + nf*8 + tig*2;
        float cs0 = c_s[r], cs1 = c_s[r+8];
        float v00 = (acc[0][nf][0]*acc[1][nf][0] - acc[2][nf][0]*acc[3][nf][0]) * cs0;
        float v01 = (acc[0][nf][1]*acc[1][nf][1] - acc[2][nf][1]*acc[3][nf][1]) * cs0;
        float v10 = (acc[0][nf][2]*acc[1][nf][2] - acc[2][nf][2]*acc[3][nf][2]) * cs1;
        float v11 = (acc[0][nf][3]*acc[1][nf][3] - acc[2][nf][3]*acc[3][nf][3]) * cs1;
        size_t o0 = (r0 + r)*128 + c;
        size_t o1 = o0 + (size_t)8*128;
        st_pair(g_hgh+o0, g_hgl+o0, v00, v01);
        st_pair(g_hgh+o1, g_hgl+o1, v10, v11);
    }
}

// ---------------- MLP1: x1[r,o0:o0+64] = cat @ W1^T + b1; K=384, 2-stage pipeline ----------------
__global__ __launch_bounds__(256) void k_mlp1_c(const float* __restrict__ b1) {
    int o0 = blockIdx.x * 64;
    size_t r0 = (size_t)blockIdx.y * 128;
    extern __shared__ __align__(256) char smem[];
    uint32_t sb = s2u(smem);
    int t = threadIdx.x, w = t>>5, lane = t&31;
    int m0w = (w&3)*32, n0w = (w>>2)*32;
    int gid = lane>>2, tig = lane&3;

    float acc[2][4][4];
#pragma unroll
    for (int i=0;i<2;i++)
#pragma unroll
        for (int j=0;j<4;j++)
#pragma unroll
            for (int q=0;q<4;q++) acc[i][j][q]=0.f;

    auto load_chunk = [&](int c, int buf){
        uint32_t st = sb + buf*49152;
        const __nv_bfloat16 *ah = (c<2) ? g_hh : (c<4) ? g_hph : g_hgh;
        const __nv_bfloat16 *al = (c<2) ? g_hl : (c<4) ? g_hpl : g_hgl;
        int off = (c&1)*64;
        cpa_tile128(st,        ah + r0*128 + off, 128, 128, t, 256);
        cpa_tile128(st+16384,  al + r0*128 + off, 128, 128, t, 256);
        cpa_tile128(st+32768,  g_W1h + (size_t)o0*384 + c*64, 64, 384, t, 256);
        cpa_tile128(st+40960,  g_W1l + (size_t)o0*384 + c*64, 64, 384, t, 256);
        CP_COMMIT();
    };
    load_chunk(0, 0);
    for (int c = 0; c < 6; c++) {
        if (c < 5) load_chunk(c+1, (c+1)&1);
        if (c < 5) { CP_WAIT1(); } else { CP_WAIT0(); }
        __syncthreads();
        uint32_t st = sb + (c&1)*49152;
#pragma unroll
        for (int ks = 0; ks < 4; ks++) {
            uint32_t ah[2][4], al[2][4];
#pragma unroll
            for (int mf=0; mf<2; mf++){
                ldA128(ah[mf], st,       m0w+mf*16, ks, lane);
                ldA128(al[mf], st+16384, m0w+mf*16, ks, lane);
            }
#pragma unroll
            for (int nf=0; nf<4; nf++){
                uint32_t bh[2], bl[2];
                ldB128(bh, st+32768, n0w+nf*8, ks, lane);
                ldB128(bl, st+40960, n0w+nf*8, ks, lane);
#pragma unroll
                for (int mf=0; mf<2; mf++){
                    mmab(acc[mf][nf], ah[mf], bh);
                    mmab(acc[mf][nf], ah[mf], bl);
                    mmab(acc[mf][nf], al[mf], bh);
                }
            }
        }
        __syncthreads();
    }
    float* dst = g_x1 + r0*256 + o0;
#pragma unroll
    for (int mf=0; mf<2; mf++)
#pragma unroll
        for (int nf=0; nf<4; nf++){
            int r = m0w + mf*16 + gid, c = n0w + nf*8 + tig*2;
            float bb0 = b1[o0+c], bb1 = b1[o0+c+1];
            float2 lo; lo.x = acc[mf][nf][0] + bb0; lo.y = acc[mf][nf][1] + bb1;
            float2 hi; hi.x = acc[mf][nf][2] + bb0; hi.y = acc[mf][nf][3] + bb1;
            *(float2*)(dst + (size_t)r*256 + c)     = lo;
            *(float2*)(dst + (size_t)(r+8)*256 + c) = hi;
        }
}

// ---------------- BN stats / finalize ----------------
__global__ void k_stats1() {
    int t = threadIdx.x;
    int r0 = blockIdx.x * 512;
    float s = 0.f, s2 = 0.f;
    for (int r = r0; r < r0 + 512; r++) {
        float v = g_x1[(size_t)r*256 + t];
        s += v; s2 += v*v;
    }
    atomicAdd(&g_sum1[t], s);
    atomicAdd(&g_sq1[t], s2);
}
__global__ void k_fin1(const float* __restrict__ gamma, const float* __restrict__ beta) {
    int t = threadIdx.x;
    if (t < 256) {
        float mean = g_sum1[t] / (float)BV;
        float var  = g_sq1[t] / (float)BV - mean*mean;
        float inv  = rsqrtf(var + 1e-5f);
        float sc   = gamma[t]*inv;
        g_scale1[t] = sc;
        g_shift1[t] = beta[t] - mean*sc;
    }
}
__global__ void k_actsplit() {
    size_t i = (size_t)blockIdx.x*blockDim.x + threadIdx.x;
    if (i < (size_t)BV*256) {
        int c = (int)(i & 255);
        float v = fmaxf(g_x1[i]*g_scale1[c] + g_shift1[c], 0.f);
        splitf(v, g_a1h[i], g_a1l[i]);
    }
}
__global__ void k_stats2() {
    int t = threadIdx.x;
    int r0 = blockIdx.x * 512;
    float s = 0.f, s2 = 0.f;
    for (int r = r0; r < r0 + 512; r++) {
        float v = g_x2[(size_t)r*128 + t];
        s += v; s2 += v*v;
    }
    atomicAdd(&g_sum2[t], s);
    atomicAdd(&g_sq2[t], s2);
}
__global__ void k_fin2(const float* __restrict__ gamma, const float* __restrict__ beta) {
    int t = threadIdx.x;
    if (t < 128) {
        float mean = g_sum2[t] / (float)BV;
        float var  = g_sq2[t] / (float)BV - mean*mean;
        float inv  = rsqrtf(var + 1e-5f);
        float sc   = gamma[t]*inv;
        g_scale2[t] = sc;
        g_shift2[t] = beta[t] - mean*sc;
    }
}

// ---------------- MLP2: x2 = act @ W2^T + b2; K=256, 2-stage pipeline ----------------
__global__ __launch_bounds__(256) void k_mlp2_c(const float* __restrict__ b2) {
    int h0 = blockIdx.x * 64;
    size_t r0 = (size_t)blockIdx.y * 128;
    extern __shared__ __align__(256) char smem[];
    uint32_t sb = s2u(smem);
    int t = threadIdx.x, w = t>>5, lane = t&31;
    int m0w = (w&3)*32, n0w = (w>>2)*32;
    int gid = lane>>2, tig = lane&3;

    float acc[2][4][4];
#pragma unroll
    for (int i=0;i<2;i++)
#pragma unroll
        for (int j=0;j<4;j++)
#pragma unroll
            for (int q=0;q<4;q++) acc[i][j][q]=0.f;

    auto load_chunk = [&](int c, int buf){
        uint32_t st = sb + buf*49152;
        cpa_tile128(st,        g_a1h + r0*256 + c*64, 128, 256, t, 256);
        cpa_tile128(st+16384,  g_a1l + r0*256 + c*64, 128, 256, t, 256);
        cpa_tile128(st+32768,  g_W2h + (size_t)h0*256 + c*64, 64, 256, t, 256);
        cpa_tile128(st+40960,  g_W2l + (size_t)h0*256 + c*64, 64, 256, t, 256);
        CP_COMMIT();
    };
    load_chunk(0, 0);
    for (int c = 0; c < 4; c++) {
        if (c < 3) load_chunk(c+1, (c+1)&1);
        if (c < 3) { CP_WAIT1(); } else { CP_WAIT0(); }
        __syncthreads();
        uint32_t st = sb + (c&1)*49152;
#pragma unroll
        for (int ks = 0; ks < 4; ks++) {
            uint32_t ah[2][4], al[2][4];
#pragma unroll
            for (int mf=0; mf<2; mf++){
                ldA128(ah[mf], st,       m0w+mf*16, ks, lane);
                ldA128(al[mf], st+16384, m0w+mf*16, ks, lane);
            }
#pragma unroll
            for (int nf=0; nf<4; nf++){
                uint32_t bh[2], bl[2];
                ldB128(bh, st+32768, n0w+nf*8, ks, lane);
                ldB128(bl, st+40960, n0w+nf*8, ks, lane);
#pragma unroll
                for (int mf=0; mf<2; mf++){
                    mmab(acc[mf][nf], ah[mf], bh);
                    mmab(acc[mf][nf], ah[mf], bl);
                    mmab(acc[mf][nf], al[mf], bh);
                }
            }
        }
        __syncthreads();
    }
    float* dst = g_x2 + r0*128 + h0;
#pragma unroll
    for (int mf=0; mf<2; mf++)
#pragma unroll
        for (int nf=0; nf<4; nf++){
            int r = m0w + mf*16 + gid, c = n0w + nf*8 + tig*2;
            float bb0 = b2[h0+c], bb1 = b2[h0+c+1];
            float2 lo; lo.x = acc[mf][nf][0] + bb0; lo.y = acc[mf][nf][1] + bb1;
            float2 hi; hi.x = acc[mf][nf][2] + bb0; hi.y = acc[mf][nf][3] + bb1;
            *(float2*)(dst + (size_t)r*128 + c)     = lo;
            *(float2*)(dst + (size_t)(r+8)*128 + c) = hi;
        }
}

// ---------------- final: out = h + bn2(x2) ----------------
__global__ void k_final(const float* __restrict__ h, float* __restrict__ out) {
    size_t i = (size_t)blockIdx.x*blockDim.x + threadIdx.x;
    if (i < (size_t)BV*NH) {
        int c = (int)(i & 127);
        out[i] = h[i] + g_scale2[c]*g_x2[i] + g_shift2[c];
    }
}

// ---------------- launch ----------------
extern "C" void kernel_launch(void* const* d_in, const int* in_sizes, int n_in,
                              void* d_out, int out_size) {
    const float* h      = (const float*)d_in[0];
    const float* eigs   = (const float*)d_in[1];
    const float* gvals  = (const float*)d_in[2];
    const int*   gidx   = (const int*)  d_in[3];
    const float* gbasis = (const float*)d_in[4];
    const float* vnorm  = (const float*)d_in[5];
    const float* ptime  = (const float*)d_in[6];
    const float* bem    = (const float*)d_in[7];
    const float* bes    = (const float*)d_in[8];
    const float* Wg     = (const float*)d_in[9];
    const float* Wg2    = (const float*)d_in[10];
    const float* W1     = (const float*)d_in[11];
    const float* b1     = (const float*)d_in[12];
    const float* gamma1 = (const float*)d_in[13];
    const float* beta1  = (const float*)d_in[14];
    const float* W2     = (const float*)d_in[15];
    const float* b2     = (const float*)d_in[16];
    const float* gamma2 = (const float*)d_in[17];
    const float* beta2  = (const float*)d_in[18];
    float* out = (float*)d_out;

    const int SM_SPECUP = 98304;
    const int SM_GRAD   = 196608;
    const int SM_MLP    = 98304;
    const int SM_SD     = 131072;
    cudaFuncSetAttribute(k_specup_c,   cudaFuncAttributeMaxDynamicSharedMemorySize, SM_SPECUP);
    cudaFuncSetAttribute(k_gradcomb_c, cudaFuncAttributeMaxDynamicSharedMemorySize, SM_GRAD);
    cudaFuncSetAttribute(k_mlp1_c,     cudaFuncAttributeMaxDynamicSharedMemorySize, SM_MLP);
    cudaFuncSetAttribute(k_mlp2_c,     cudaFuncAttributeMaxDynamicSharedMemorySize, SM_MLP);
    cudaFuncSetAttribute(k_sdmma,      cudaFuncAttributeMaxDynamicSharedMemorySize, SM_SD);

    k_zero<<<256, 256>>>();
    k_prep1<<<(163840 + 2*NVK + 255)/256, 256>>>(W1, W2, Wg, Wg2, eigs, h);
    k_transpose<<<dim3(NV/32, 8, NB), dim3(32, 8)>>>(eigs, h);
    k_sdmma<<<dim3(VCH, NB), 256, SM_SD>>>();
    k_modulate<<<dim3(NK, NB), NH>>>(eigs, ptime, bem, bes);
    k_specup_c<<<dim3(2, NV/128, NB), 256, SM_SPECUP>>>();
    k_count<<<(NB*NNZV + 255)/256, 256>>>(gidx);
    k_scan<<<NB, 1024>>>();
    k_scatter<<<(NB*NNZV + 255)/256, 256>>>(gidx);
    k_gather<<<BV/8, 256>>>(h, gvals, gidx);
    k_gradcomb_c<<<BV/64, 512, SM_GRAD>>>(gbasis, vnorm);
    k_mlp1_c<<<dim3(4, BV/128), 256, SM_MLP>>>(b1);
    k_stats1<<<128, 256>>>();
    k_fin1<<<1, 256>>>(gamma1, beta1);
    k_actsplit<<<(int)(((size_t)BV*256 + 255)/256), 256>>>();
    k_mlp2_c<<<dim3(2, BV/128), 256, SM_MLP>>>(b2);
    k_stats2<<<128, 128>>>();
    k_fin2<<<1, 128>>>(gamma2, beta2);
    k_final<<<(int)(((size_t)BV*NH + 255)/256), 256>>>(h, out);
}